// round 17
// baseline (speedup 1.0000x reference)
#include <cuda_runtime.h>
#include <cuda_bf16.h>
#include <cstdint>

// ---------------------------------------------------------------------------
// EdgeAlignmentModule — generation-tagged hash join with IN-SLOT features.
// 2 launches (insert -> lookup) overlapped with PDL. No reset, no cleanup.
//
//   key(src,dst) = src * total_nodes + dst   (< 1e8, fits in 27 bits)
//   Slot = 32B, two 16B halves, each {tag, payload}:
//       tag     (64b) = gen(18) << 46 | key(27) << 19 | idx(19)
//       payload (64b) = half A: {f1,f0} = edge_attr_old[.,1],[.,0]
//                       half B: {f3,f2} = flow_old, edge_attr_old[.,2]
//   Each half is updated ONLY via atom.cas.b128, so tag+payload change
//   atomically: duplicate keys resolve to MAX old index WITH its features
//   (== sequential-scatter "last wins" of table.at[old_keys].set(arange)),
//   no separate feature array, no write race.
//
// Stale slots (gen field != current gen) are EMPTY; claimed by CAS against
// the observed word. Per-call gen derives on-device from a per-kernel
// counter (one bump per block; stream ordering partitions arrivals per
// call). Table starts zeroed (gen 0 = stale); first call uses gen 1.
//
// Lookup probe = two INDEPENDENT 16B loads of one 32B slot (single memory
// epoch) -> tag check -> features already in registers. The old chain
// idx -> probe -> gather -> store loses the gather epoch entirely.
// ---------------------------------------------------------------------------

#define TABLE_LOG2 20
#define TABLE_SIZE (1u << TABLE_LOG2)
#define TABLE_MASK (TABLE_SIZE - 1u)

#define GEN_SHIFT 46
#define KEY_SHIFT 19
#define KEY_MASK  0x7FFFFFFull
#define IDX_MASK  ((1ull << KEY_SHIFT) - 1ull)

#define NTHREADS 256

struct __align__(32) Slot {
    ulonglong2 a;   // {tag, feats01}
    ulonglong2 b;   // {tag, feats23}
};

__device__ Slot g_tab[TABLE_SIZE];                 // 32MB, zero-init: gen 0
__device__ unsigned long long g_ctr_ins;           // insert call counter
__device__ unsigned long long g_ctr_lkp;           // lookup call counter

__device__ __forceinline__ uint32_t hash_key(uint32_t key) {
    return (key * 0x9E3779B1u) >> (32 - TABLE_LOG2);
}

__device__ __forceinline__ unsigned long long
block_gen(unsigned long long* ctr) {
    __shared__ unsigned long long s_gen;
    if (threadIdx.x == 0) {
        unsigned long long t = atomicAdd(ctr, 1ull);
        s_gen = t / gridDim.x + 1ull;   // same for every block of a call
    }
    __syncthreads();
    return s_gen;
}

// 128-bit compare-and-swap (sm_90+). Returns the observed old value.
__device__ __forceinline__ ulonglong2
cas128(ulonglong2* p, ulonglong2 cmp, ulonglong2 val) {
    ulonglong2 old;
    asm volatile(
        "{\n\t"
        ".reg .b128 o, c, v;\n\t"
        "mov.b128 c, {%2, %3};\n\t"
        "mov.b128 v, {%4, %5};\n\t"
        "atom.cas.b128 o, [%6], c, v;\n\t"
        "mov.b128 {%0, %1}, o;\n\t"
        "}"
        : "=l"(old.x), "=l"(old.y)
        : "l"(cmp.x), "l"(cmp.y), "l"(val.x), "l"(val.y), "l"(p)
        : "memory");
    return old;
}

__device__ __forceinline__ unsigned long long pack2(float lo, float hi) {
    return ((unsigned long long)__float_as_uint(hi) << 32)
         | (unsigned long long)__float_as_uint(lo);
}

// ---- Kernel 1 (primary): insert old edges, features in-slot ----------------
__global__ __launch_bounds__(NTHREADS)
void insert_kernel(const int*   __restrict__ edge_index_old,
                   const float* __restrict__ edge_attr_old,
                   const float* __restrict__ flow_old,
                   int E_old, int total_nodes) {
    cudaTriggerProgrammaticLaunchCompletion();   // let lookup grid launch now

    const unsigned long long gen = block_gen(&g_ctr_ins);
    int i = blockIdx.x * NTHREADS + threadIdx.x;
    if (i >= E_old) return;

    // Independent loads up front.
    int src = __ldg(edge_index_old + i);
    int dst = __ldg(edge_index_old + E_old + i);
    const float* ea = edge_attr_old + (size_t)i * 3;
    float f0 = __ldg(ea + 0);
    float f1 = __ldg(ea + 1);
    float f2 = __ldg(ea + 2);
    float f3 = __ldg(flow_old + i);

    uint32_t key = (uint32_t)(src * total_nodes + dst);
    const unsigned long long tag =
        (gen << GEN_SHIFT) | ((unsigned long long)key << KEY_SHIFT)
        | (unsigned long long)(uint32_t)i;
    ulonglong2 mineA; mineA.x = tag; mineA.y = pack2(f0, f1);
    ulonglong2 mineB; mineB.x = tag; mineB.y = pack2(f2, f3);

    // Resolve half A (walks the probe chain). Any same-gen tag observed is
    // current-call truth (L1 flushed per launch; slot idx is monotone).
    uint32_t h = hash_key(key);
    ulonglong2 cur = g_tab[h].a;     // possibly stale; CAS validates
    bool winner = false;
    while (true) {
        unsigned long long t = cur.x;
        if ((t >> GEN_SHIFT) == gen) {
            if ((uint32_t)((t >> KEY_SHIFT) & KEY_MASK) != key) {
                h = (h + 1) & TABLE_MASK;    // other key: linear probe
                cur = g_tab[h].a;
                continue;
            }
            if ((uint32_t)(t & IDX_MASK) > (uint32_t)i) break;  // bigger owns it
        }
        ulonglong2 old = cas128(&g_tab[h].a, cur, mineA);
        if (old.x == cur.x && old.y == cur.y) { winner = true; break; }
        cur = old;                           // fresh value; retry same slot
    }

    // Half B at the same slot: only stale or same-key words ever live here.
    if (winner) {
        ulonglong2 cur2 = g_tab[h].b;
        while (true) {
            unsigned long long t = cur2.x;
            if ((t >> GEN_SHIFT) == gen &&
                (uint32_t)(t & IDX_MASK) > (uint32_t)i) break;
            ulonglong2 old = cas128(&g_tab[h].b, cur2, mineB);
            if (old.x == cur2.x && old.y == cur2.y) break;
            cur2 = old;
        }
    }
}

// ---- Kernel 2 (dependent): lookup, features from slot, emit [E_new, 8] -----
__global__ __launch_bounds__(NTHREADS)
void lookup_emit_kernel(const int*   __restrict__ edge_index_new,
                        const float* __restrict__ edge_attr_new,
                        float*       __restrict__ out,
                        int E_new, int total_nodes) {
    const unsigned long long gen = block_gen(&g_ctr_lkp);
    int i = blockIdx.x * NTHREADS + threadIdx.x;

    // Prologue: table-independent loads (overlap with insert via PDL).
    int src = 0, dst = 0;
    float n0 = 0.f, n1 = 0.f, n2 = 0.f;
    if (i < E_new) {
        src = __ldg(edge_index_new + i);
        dst = __ldg(edge_index_new + E_new + i);
        const float* en = edge_attr_new + (size_t)i * 3;
        n0 = __ldg(en + 0); n1 = __ldg(en + 1); n2 = __ldg(en + 2);
    }
    uint32_t key = (uint32_t)(src * total_nodes + dst);
    uint32_t h = hash_key(key);

    cudaGridDependencySynchronize();   // table fully built + visible

    if (i >= E_new) return;

    float4 a = make_float4(0.f, 0.f, 0.f, 0.f);
    float flag = 1.f;   // is_new_edge
    while (true) {
        // Both halves issued independently: one 32B slot, one memory epoch.
        ulonglong2 wa = __ldg((const ulonglong2*)&g_tab[h].a);
        ulonglong2 wb = __ldg((const ulonglong2*)&g_tab[h].b);
        unsigned long long t = wa.x;
        if ((t >> GEN_SHIFT) != gen) break;              // empty: miss
        if ((uint32_t)((t >> KEY_SHIFT) & KEY_MASK) == key) {
            a.x = __uint_as_float((uint32_t)wa.y);
            a.y = __uint_as_float((uint32_t)(wa.y >> 32));
            a.z = __uint_as_float((uint32_t)wb.y);
            a.w = __uint_as_float((uint32_t)(wb.y >> 32));
            flag = 0.f;
            break;
        }
        h = (h + 1) & TABLE_MASK;
    }

    float4* o = reinterpret_cast<float4*>(out + (size_t)i * 8);
    o[0] = a;
    o[1] = make_float4(n0, n1, n2, flag);
}

extern "C" void kernel_launch(void* const* d_in, const int* in_sizes, int n_in,
                              void* d_out, int out_size) {
    const int*   edge_index_old = (const int*)  d_in[0];
    const float* edge_attr_old  = (const float*)d_in[1];
    const float* flow_old       = (const float*)d_in[2];
    const int*   edge_index_new = (const int*)  d_in[3];
    const float* edge_attr_new  = (const float*)d_in[4];
    (void)n_in; (void)out_size;

    int E_old = in_sizes[1] / 3;   // edge_attr_old is [E_old, 3]
    int E_new = in_sizes[4] / 3;   // edge_attr_new is [E_new, 3]
    int total_nodes = 10000;       // fixed by problem; key fits in 27 bits

    // Primary: plain launch.
    insert_kernel<<<(E_old + NTHREADS - 1) / NTHREADS, NTHREADS>>>(
        edge_index_old, edge_attr_old, flow_old, E_old, total_nodes);

    // Dependent: PDL launch — overlaps its prologue with insert.
    {
        cudaLaunchConfig_t cfg = {};
        cfg.gridDim  = dim3((E_new + NTHREADS - 1) / NTHREADS);
        cfg.blockDim = dim3(NTHREADS);
        cfg.dynamicSmemBytes = 0;
        cfg.stream = 0;

        cudaLaunchAttribute attr[1];
        attr[0].id = cudaLaunchAttributeProgrammaticStreamSerialization;
        attr[0].val.programmaticStreamSerializationAllowed = 1;
        cfg.attrs = attr;
        cfg.numAttrs = 1;

        cudaLaunchKernelEx(&cfg, lookup_emit_kernel,
                           edge_index_new, edge_attr_new, (float*)d_out,
                           E_new, total_nodes);
    }
}